// round 4
// baseline (speedup 1.0000x reference)
#include <cuda_runtime.h>
#include <cstdint>

#define NMAX   50000
#define HID    128
#define KT     16

// ---------------- scratch (no allocations allowed) ----------------
__device__ __align__(16) float g_msg [(size_t)NMAX * HID];   // h @ W_edge^T
__device__ __align__(16) float g_self[(size_t)NMAX * HID];   // h @ W_self^T + b
__device__ __align__(16) float g_sums[(size_t)NMAX * HID];   // segment_sum(msg[src], dst)
__device__ __align__(16) float g_deg [NMAX];                 // in-degree (float)

// ---------------- zero scratch ----------------
__global__ void zero_kernel(int n) {
    long long total4 = (long long)n * (HID / 4);
    float4 z = make_float4(0.f, 0.f, 0.f, 0.f);
    float4* s4 = reinterpret_cast<float4*>(g_sums);
    for (long long i = blockIdx.x * (long long)blockDim.x + threadIdx.x;
         i < total4; i += (long long)gridDim.x * blockDim.x)
        s4[i] = z;
    for (int i = blockIdx.x * blockDim.x + threadIdx.x; i < n;
         i += gridDim.x * blockDim.x)
        g_deg[i] = 0.f;
}

// ---------------- SGEMM: C[M,128] = A[M,128] @ W[128,128]^T (+bias) ----------------
// Block: 256 threads (16x16 logical). Each block computes 128 rows x 128 cols.
// Register tile 8x8 per thread; K split into KT=16 tiles staged in smem,
// both A and W stored transposed (k-major) so compute reads are float4.
template<bool SELF>
__global__ void gemm128(const float* __restrict__ A,
                        const float* __restrict__ W,
                        const float* __restrict__ bias,
                        int M) {
    __shared__ float At[KT][132];   // At[k][row]
    __shared__ float Wt[KT][132];   // Wt[k][col]

    const int t  = threadIdx.x;
    const int tx = t & 15;          // col group
    const int ty = t >> 4;          // row group
    const int row0 = blockIdx.x * 128;

    float acc[8][8];
#pragma unroll
    for (int i = 0; i < 8; i++)
#pragma unroll
        for (int j = 0; j < 8; j++) acc[i][j] = 0.f;

    for (int k0 = 0; k0 < HID; k0 += KT) {
        // Stage tiles: 128 rows x 16 k each = 512 float4 per array, 2 per thread.
#pragma unroll
        for (int it = 0; it < 2; it++) {
            int idx = t + it * 256;       // 0..511
            int r   = idx >> 2;           // 0..127  (row for A, col j for W)
            int q   = idx & 3;            // k-quad within tile
            int kk  = q * 4;

            float4 v = make_float4(0.f, 0.f, 0.f, 0.f);
            int row = row0 + r;
            if (row < M)
                v = *reinterpret_cast<const float4*>(A + (long long)row * HID + k0 + kk);
            At[kk + 0][r] = v.x; At[kk + 1][r] = v.y;
            At[kk + 2][r] = v.z; At[kk + 3][r] = v.w;

            float4 w = *reinterpret_cast<const float4*>(W + r * HID + k0 + kk);
            Wt[kk + 0][r] = w.x; Wt[kk + 1][r] = w.y;
            Wt[kk + 2][r] = w.z; Wt[kk + 3][r] = w.w;
        }
        __syncthreads();

#pragma unroll
        for (int kk = 0; kk < KT; kk++) {
            float a[8], b[8];
            *reinterpret_cast<float4*>(a)     = *reinterpret_cast<const float4*>(&At[kk][ty * 8]);
            *reinterpret_cast<float4*>(a + 4) = *reinterpret_cast<const float4*>(&At[kk][ty * 8 + 4]);
            *reinterpret_cast<float4*>(b)     = *reinterpret_cast<const float4*>(&Wt[kk][tx * 8]);
            *reinterpret_cast<float4*>(b + 4) = *reinterpret_cast<const float4*>(&Wt[kk][tx * 8 + 4]);
#pragma unroll
            for (int i = 0; i < 8; i++)
#pragma unroll
                for (int j = 0; j < 8; j++)
                    acc[i][j] += a[i] * b[j];
        }
        __syncthreads();
    }

    // bias (self path only)
    float bv[8];
    if (SELF) {
#pragma unroll
        for (int j = 0; j < 8; j++) bv[j] = bias[tx * 8 + j];
    }

    float* C = SELF ? g_self : g_msg;
#pragma unroll
    for (int i = 0; i < 8; i++) {
        int row = row0 + ty * 8 + i;
        if (row >= M) break;
        float* cp = C + (long long)row * HID + tx * 8;
        float o[8];
#pragma unroll
        for (int j = 0; j < 8; j++)
            o[j] = SELF ? (acc[i][j] + bv[j]) : acc[i][j];
        *reinterpret_cast<float4*>(cp)     = *reinterpret_cast<const float4*>(o);
        *reinterpret_cast<float4*>(cp + 4) = *reinterpret_cast<const float4*>(o + 4);
    }
}

// ---------------- edge scatter: sums[dst] += msg[src]; deg[dst] += 1 ----------------
// One warp per edge: lane handles 4 contiguous floats; vector red (no return).
// Indices are INT32 (JAX default x64-disabled downcasts int64 -> int32).
__global__ void edge_kernel(const int* __restrict__ src,
                            const int* __restrict__ dst,
                            int E, int N) {
    int warp = (blockIdx.x * blockDim.x + threadIdx.x) >> 5;
    int lane = threadIdx.x & 31;
    if (warp >= E) return;

    int s = src[warp];
    int d = dst[warp];
    // Defensive: if dtype assumption is wrong we produce a wrong (diagnosable)
    // answer rather than an illegal access.
    if ((unsigned)s >= (unsigned)N || (unsigned)d >= (unsigned)N) return;

    const float4 v = *reinterpret_cast<const float4*>(g_msg + (size_t)s * HID + lane * 4);
    float* p = g_sums + (size_t)d * HID + lane * 4;
    asm volatile("red.global.add.v4.f32 [%0], {%1,%2,%3,%4};"
                 :: "l"(p), "f"(v.x), "f"(v.y), "f"(v.z), "f"(v.w)
                 : "memory");
    if (lane == 0) {
        asm volatile("red.global.add.f32 [%0], %1;"
                     :: "l"(g_deg + d), "f"(1.0f) : "memory");
    }
}

// ---------------- finalize: out = relu(self + sums / max(deg,1)) ----------------
__global__ void finalize_kernel(float* __restrict__ out, int n) {
    int i = blockIdx.x * blockDim.x + threadIdx.x;   // one float4 per thread
    long long total4 = (long long)n * (HID / 4);
    if (i >= total4) return;
    int node = i >> 5;                                // 32 float4 per row
    float dg  = g_deg[node];
    float inv = 1.0f / fmaxf(dg, 1.0f);
    float4 s  = reinterpret_cast<const float4*>(g_sums)[i];
    float4 sp = reinterpret_cast<const float4*>(g_self)[i];
    float4 o;
    o.x = fmaxf(fmaf(s.x, inv, sp.x), 0.f);
    o.y = fmaxf(fmaf(s.y, inv, sp.y), 0.f);
    o.z = fmaxf(fmaf(s.z, inv, sp.z), 0.f);
    o.w = fmaxf(fmaf(s.w, inv, sp.w), 0.f);
    reinterpret_cast<float4*>(out)[i] = o;
}

// ---------------- launch ----------------
extern "C" void kernel_launch(void* const* d_in, const int* in_sizes, int n_in,
                              void* d_out, int out_size) {
    const float* h   = (const float*)d_in[0];
    const int*   src = (const int*)d_in[1];
    const int*   dst = (const int*)d_in[2];
    const float* We  = (const float*)d_in[3];
    const float* Ws  = (const float*)d_in[4];
    const float* b   = (const float*)d_in[5];
    float* out = (float*)d_out;

    const int N = in_sizes[0] / HID;   // 50000
    const int E = in_sizes[1];         // 800000

    zero_kernel<<<1184, 256>>>(N);                               // 8 blocks/SM
    gemm128<false><<<(N + 127) / 128, 256>>>(h, We, nullptr, N); // msg
    gemm128<true ><<<(N + 127) / 128, 256>>>(h, Ws, b, N);       // self + bias
    edge_kernel<<<(E + 7) / 8, 256>>>(src, dst, E, N);           // 1 warp/edge
    finalize_kernel<<<((N * (HID / 4)) + 255) / 256, 256>>>(out, N);
}

// round 5
// speedup vs baseline: 1.1130x; 1.1130x over previous
#include <cuda_runtime.h>
#include <cstdint>

#define NMAX   50000
#define HID    128
#define KT     16
#define EPW    4      // edges per warp in edge_kernel

// ---------------- scratch (no allocations allowed) ----------------
__device__ __align__(16) float g_msg [(size_t)NMAX * HID];   // h @ W_edge^T
__device__ __align__(16) float g_self[(size_t)NMAX * HID];   // h @ W_self^T + b
__device__ __align__(16) float g_sums[(size_t)NMAX * HID];   // segment_sum(msg[src], dst)
__device__ __align__(16) float g_deg [NMAX];                 // in-degree (float)

// ---------------- zero scratch ----------------
__global__ void zero_kernel(int n) {
    long long total4 = (long long)n * (HID / 4);
    float4 z = make_float4(0.f, 0.f, 0.f, 0.f);
    float4* s4 = reinterpret_cast<float4*>(g_sums);
    for (long long i = blockIdx.x * (long long)blockDim.x + threadIdx.x;
         i < total4; i += (long long)gridDim.x * blockDim.x)
        s4[i] = z;
    for (int i = blockIdx.x * blockDim.x + threadIdx.x; i < n;
         i += gridDim.x * blockDim.x)
        g_deg[i] = 0.f;
}

// ---------------- SGEMM: C[M,128] = A[M,128] @ W[128,128]^T (+bias) ----------------
// ~86% of the fp32 FFMA pipe ceiling already (FFMA rt_SMSP=2 on sm_103a);
// left unchanged this round.
template<bool SELF>
__global__ void gemm128(const float* __restrict__ A,
                        const float* __restrict__ W,
                        const float* __restrict__ bias,
                        int M) {
    __shared__ float At[KT][132];   // At[k][row]
    __shared__ float Wt[KT][132];   // Wt[k][col]

    const int t  = threadIdx.x;
    const int tx = t & 15;          // col group
    const int ty = t >> 4;          // row group
    const int row0 = blockIdx.x * 128;

    float acc[8][8];
#pragma unroll
    for (int i = 0; i < 8; i++)
#pragma unroll
        for (int j = 0; j < 8; j++) acc[i][j] = 0.f;

    for (int k0 = 0; k0 < HID; k0 += KT) {
#pragma unroll
        for (int it = 0; it < 2; it++) {
            int idx = t + it * 256;       // 0..511
            int r   = idx >> 2;           // 0..127
            int q   = idx & 3;            // k-quad within tile
            int kk  = q * 4;

            float4 v = make_float4(0.f, 0.f, 0.f, 0.f);
            int row = row0 + r;
            if (row < M)
                v = *reinterpret_cast<const float4*>(A + (long long)row * HID + k0 + kk);
            At[kk + 0][r] = v.x; At[kk + 1][r] = v.y;
            At[kk + 2][r] = v.z; At[kk + 3][r] = v.w;

            float4 w = *reinterpret_cast<const float4*>(W + r * HID + k0 + kk);
            Wt[kk + 0][r] = w.x; Wt[kk + 1][r] = w.y;
            Wt[kk + 2][r] = w.z; Wt[kk + 3][r] = w.w;
        }
        __syncthreads();

#pragma unroll
        for (int kk = 0; kk < KT; kk++) {
            float a[8], b[8];
            *reinterpret_cast<float4*>(a)     = *reinterpret_cast<const float4*>(&At[kk][ty * 8]);
            *reinterpret_cast<float4*>(a + 4) = *reinterpret_cast<const float4*>(&At[kk][ty * 8 + 4]);
            *reinterpret_cast<float4*>(b)     = *reinterpret_cast<const float4*>(&Wt[kk][tx * 8]);
            *reinterpret_cast<float4*>(b + 4) = *reinterpret_cast<const float4*>(&Wt[kk][tx * 8 + 4]);
#pragma unroll
            for (int i = 0; i < 8; i++)
#pragma unroll
                for (int j = 0; j < 8; j++)
                    acc[i][j] += a[i] * b[j];
        }
        __syncthreads();
    }

    float bv[8];
    if (SELF) {
#pragma unroll
        for (int j = 0; j < 8; j++) bv[j] = bias[tx * 8 + j];
    }

    float* C = SELF ? g_self : g_msg;
#pragma unroll
    for (int i = 0; i < 8; i++) {
        int row = row0 + ty * 8 + i;
        if (row >= M) break;
        float* cp = C + (long long)row * HID + tx * 8;
        float o[8];
#pragma unroll
        for (int j = 0; j < 8; j++)
            o[j] = SELF ? (acc[i][j] + bv[j]) : acc[i][j];
        *reinterpret_cast<float4*>(cp)     = *reinterpret_cast<const float4*>(o);
        *reinterpret_cast<float4*>(cp + 4) = *reinterpret_cast<const float4*>(o + 4);
    }
}

// ---------------- edge scatter: sums[dst] += msg[src]; deg[dst] += 1 ----------------
// EPW=4 edges per warp. Indices fetched as one int4 per array (vector LDG),
// then 4 independent LDG.128 feature loads issue before the 4 REDs -> MLP 4x.
__global__ void edge_kernel(const int* __restrict__ src,
                            const int* __restrict__ dst,
                            int E, int N) {
    int warp = (blockIdx.x * blockDim.x + threadIdx.x) >> 5;
    int lane = threadIdx.x & 31;
    int base = warp * EPW;
    if (base >= E) return;

    int s[EPW], d[EPW];
    if (base + EPW <= E) {
        int4 sv = *reinterpret_cast<const int4*>(src + base);
        int4 dv = *reinterpret_cast<const int4*>(dst + base);
        s[0] = sv.x; s[1] = sv.y; s[2] = sv.z; s[3] = sv.w;
        d[0] = dv.x; d[1] = dv.y; d[2] = dv.z; d[3] = dv.w;
    } else {
#pragma unroll
        for (int e = 0; e < EPW; e++) {
            int i = base + e;
            s[e] = (i < E) ? src[i] : 0;
            d[e] = (i < E) ? dst[i] : -1;   // -1 -> skipped by range guard
        }
    }

    // Gather: 4 independent 16B loads per lane (front-batched for MLP).
    float4 v[EPW];
#pragma unroll
    for (int e = 0; e < EPW; e++) {
        int ss = ((unsigned)s[e] < (unsigned)N) ? s[e] : 0;
        v[e] = *reinterpret_cast<const float4*>(g_msg + (size_t)ss * HID + lane * 4);
    }

    // Scatter: vector reductions (no return trip).
#pragma unroll
    for (int e = 0; e < EPW; e++) {
        if ((unsigned)d[e] >= (unsigned)N || (unsigned)s[e] >= (unsigned)N) continue;
        float* p = g_sums + (size_t)d[e] * HID + lane * 4;
        asm volatile("red.global.add.v4.f32 [%0], {%1,%2,%3,%4};"
                     :: "l"(p), "f"(v[e].x), "f"(v[e].y), "f"(v[e].z), "f"(v[e].w)
                     : "memory");
    }

    // Degree: lanes 0..EPW-1 each bump one destination.
    if (lane < EPW) {
        int dd = d[lane];
        if ((unsigned)dd < (unsigned)N && base + lane < E) {
            asm volatile("red.global.add.f32 [%0], %1;"
                         :: "l"(g_deg + dd), "f"(1.0f) : "memory");
        }
    }
}

// ---------------- finalize: out = relu(self + sums / max(deg,1)) ----------------
__global__ void finalize_kernel(float* __restrict__ out, int n) {
    int i = blockIdx.x * blockDim.x + threadIdx.x;   // one float4 per thread
    long long total4 = (long long)n * (HID / 4);
    if (i >= total4) return;
    int node = i >> 5;                                // 32 float4 per row
    float dg  = g_deg[node];
    float inv = 1.0f / fmaxf(dg, 1.0f);
    float4 s  = reinterpret_cast<const float4*>(g_sums)[i];
    float4 sp = reinterpret_cast<const float4*>(g_self)[i];
    float4 o;
    o.x = fmaxf(fmaf(s.x, inv, sp.x), 0.f);
    o.y = fmaxf(fmaf(s.y, inv, sp.y), 0.f);
    o.z = fmaxf(fmaf(s.z, inv, sp.z), 0.f);
    o.w = fmaxf(fmaf(s.w, inv, sp.w), 0.f);
    reinterpret_cast<float4*>(out)[i] = o;
}

// ---------------- launch ----------------
extern "C" void kernel_launch(void* const* d_in, const int* in_sizes, int n_in,
                              void* d_out, int out_size) {
    const float* h   = (const float*)d_in[0];
    const int*   src = (const int*)d_in[1];
    const int*   dst = (const int*)d_in[2];
    const float* We  = (const float*)d_in[3];
    const float* Ws  = (const float*)d_in[4];
    const float* b   = (const float*)d_in[5];
    float* out = (float*)d_out;

    const int N = in_sizes[0] / HID;   // 50000
    const int E = in_sizes[1];         // 800000

    zero_kernel<<<1184, 256>>>(N);
    gemm128<false><<<(N + 127) / 128, 256>>>(h, We, nullptr, N); // msg
    gemm128<true ><<<(N + 127) / 128, 256>>>(h, Ws, b, N);       // self + bias

    int warps_needed  = (E + EPW - 1) / EPW;                     // 200000
    int blocks_needed = (warps_needed + 7) / 8;                  // 8 warps/block
    edge_kernel<<<blocks_needed, 256>>>(src, dst, E, N);

    finalize_kernel<<<((N * (HID / 4)) + 255) / 256, 256>>>(out, N);
}

// round 8
// speedup vs baseline: 1.2765x; 1.1469x over previous
#include <cuda_runtime.h>
#include <cuda_bf16.h>
#include <cstdint>

#define NMAX 50000
#define HID  128
#define EPW  4

// ---------------- scratch (no allocations allowed) ----------------
__device__ __align__(16) float g_msg [(size_t)NMAX * HID];
__device__ __align__(16) float g_self[(size_t)NMAX * HID];
__device__ __align__(16) float g_sums[(size_t)NMAX * HID];
__device__ __align__(16) float g_deg [NMAX];
// Pre-split bf16 hi/lo image of B = [W_edge ; W_self], plain row-major [n][k]
__device__ __align__(16) uint8_t g_Bh[256 * 128 * 2];
__device__ __align__(16) uint8_t g_Bl[256 * 128 * 2];

// ---------------- helpers ----------------
// Split two fp32 into packed bf16x2 hi and bf16x2 lo (lo = x - float(hi)).
__device__ __forceinline__ void split2(float x0, float x1, uint32_t& h, uint32_t& l) {
    uint32_t hp;
    asm("cvt.rn.bf16x2.f32 %0, %1, %2;" : "=r"(hp) : "f"(x1), "f"(x0));
    float h0 = __uint_as_float(hp << 16);
    float h1 = __uint_as_float(hp & 0xFFFF0000u);
    float l0 = x0 - h0;
    float l1 = x1 - h1;
    asm("cvt.rn.bf16x2.f32 %0, %1, %2;" : "=r"(l) : "f"(l1), "f"(l0));
    h = hp;
}

#define MMA_BF16(c, a, b0, b1)                                                  \
    asm volatile("mma.sync.aligned.m16n8k16.row.col.f32.bf16.bf16.f32 "        \
                 "{%0,%1,%2,%3}, {%4,%5,%6,%7}, {%8,%9}, {%0,%1,%2,%3};"       \
                 : "+f"((c)[0]), "+f"((c)[1]), "+f"((c)[2]), "+f"((c)[3])      \
                 : "r"((a)[0]), "r"((a)[1]), "r"((a)[2]), "r"((a)[3]),         \
                   "r"(b0), "r"(b1))

// ---------------- zero scratch ----------------
__global__ void zero_kernel(int n) {
    long long total4 = (long long)n * (HID / 4);
    float4 z = make_float4(0.f, 0.f, 0.f, 0.f);
    float4* s4 = reinterpret_cast<float4*>(g_sums);
    for (long long i = blockIdx.x * (long long)blockDim.x + threadIdx.x;
         i < total4; i += (long long)gridDim.x * blockDim.x)
        s4[i] = z;
    for (int i = blockIdx.x * blockDim.x + threadIdx.x; i < n;
         i += gridDim.x * blockDim.x)
        g_deg[i] = 0.f;
}

// ---------------- one-time B prep: bf16 hi/lo split, row-major ----------------
__global__ void prep_B(const float* __restrict__ We, const float* __restrict__ Ws) {
    int idx = blockIdx.x * blockDim.x + threadIdx.x;   // 4096 chunks of 8 k's
    if (idx >= 256 * 16) return;
    int n  = idx >> 4;
    int kc = (idx & 15) * 8;
    const float* sp = (n < 128) ? (We + n * HID + kc) : (Ws + (n - 128) * HID + kc);
    float x[8];
    *reinterpret_cast<float4*>(x)     = *reinterpret_cast<const float4*>(sp);
    *reinterpret_cast<float4*>(x + 4) = *reinterpret_cast<const float4*>(sp + 4);
    uint32_t h[4], l[4];
#pragma unroll
    for (int i = 0; i < 4; i++)
        split2(x[2 * i], x[2 * i + 1], h[i], l[i]);
    uint32_t off = (uint32_t)n * 256 + kc * 2;   // bytes, row-major [n][k] bf16
    *reinterpret_cast<uint4*>(g_Bh + off) = make_uint4(h[0], h[1], h[2], h[3]);
    *reinterpret_cast<uint4*>(g_Bl + off) = make_uint4(l[0], l[1], l[2], l[3]);
}

// ---------------- tensor-core GEMM via mma.sync (bf16x3 split) ----------------
// Grid (ceil(M/128), 2): y=0 -> g_msg (W_edge), y=1 -> g_self (W_self + bias).
// CTA: 8 warps = 128 rows x 128 cols. Warp tile 32x64 (warps 4 row x 2 col).
__global__ void __launch_bounds__(256)
gemm_mma(const float* __restrict__ A, const float* __restrict__ bias, int M) {
    const int tid  = threadIdx.x;
    const int lane = tid & 31;
    const int wid  = tid >> 5;
    const int wrow = wid & 3;
    const int wcol = wid >> 2;
    const int half = blockIdx.y;
    const int row_base = blockIdx.x * 128 + wrow * 32;
    const int g  = lane >> 2;          // 0..7
    const int t2 = (lane & 3) * 2;     // 0,2,4,6

    const uint8_t* Bh = g_Bh + (size_t)half * 128 * 256;
    const uint8_t* Bl = g_Bl + (size_t)half * 128 * 256;

    float acc[2][8][4];
#pragma unroll
    for (int mt = 0; mt < 2; mt++)
#pragma unroll
        for (int nt = 0; nt < 8; nt++)
#pragma unroll
            for (int i = 0; i < 4; i++) acc[mt][nt][i] = 0.f;

#pragma unroll
    for (int ks = 0; ks < 8; ks++) {
        const int k0 = ks * 16;

        // A fragments for both 16-row tiles, split to bf16 hi/lo in registers.
        uint32_t ahi[2][4], alo[2][4];
#pragma unroll
        for (int mt = 0; mt < 2; mt++) {
            int rA = row_base + mt * 16 + g;
            int rB = rA + 8;
            float2 v00 = make_float2(0.f, 0.f), v01 = v00, v10 = v00, v11 = v00;
            if (rA < M) {
                const float* p = A + (size_t)rA * HID + k0;
                v00 = *reinterpret_cast<const float2*>(p + t2);
                v01 = *reinterpret_cast<const float2*>(p + 8 + t2);
            }
            if (rB < M) {
                const float* p = A + (size_t)rB * HID + k0;
                v10 = *reinterpret_cast<const float2*>(p + t2);
                v11 = *reinterpret_cast<const float2*>(p + 8 + t2);
            }
            split2(v00.x, v00.y, ahi[mt][0], alo[mt][0]);
            split2(v10.x, v10.y, ahi[mt][1], alo[mt][1]);
            split2(v01.x, v01.y, ahi[mt][2], alo[mt][2]);
            split2(v11.x, v11.y, ahi[mt][3], alo[mt][3]);
        }

#pragma unroll
        for (int nt = 0; nt < 8; nt++) {
            int nrow = wcol * 64 + nt * 8 + g;             // row of B-half (= output col)
            const uint8_t* bp = Bh + (size_t)nrow * 256 + (size_t)(k0 + t2) * 2;
            const uint8_t* bq = Bl + (size_t)nrow * 256 + (size_t)(k0 + t2) * 2;
            uint32_t bh0 = *reinterpret_cast<const uint32_t*>(bp);
            uint32_t bh1 = *reinterpret_cast<const uint32_t*>(bp + 16);
            uint32_t bl0 = *reinterpret_cast<const uint32_t*>(bq);
            uint32_t bl1 = *reinterpret_cast<const uint32_t*>(bq + 16);
#pragma unroll
            for (int mt = 0; mt < 2; mt++) {
                MMA_BF16(acc[mt][nt], ahi[mt], bh0, bh1);   // hi*hi
                MMA_BF16(acc[mt][nt], ahi[mt], bl0, bl1);   // hi*lo
                MMA_BF16(acc[mt][nt], alo[mt], bh0, bh1);   // lo*hi
            }
        }
    }

    // Epilogue
    float* dstb = half ? g_self : g_msg;
#pragma unroll
    for (int mt = 0; mt < 2; mt++) {
#pragma unroll
        for (int nt = 0; nt < 8; nt++) {
            int col = wcol * 64 + nt * 8 + t2;
            float bx = 0.f, by = 0.f;
            if (half) {
                float2 bb = *reinterpret_cast<const float2*>(bias + col);
                bx = bb.x; by = bb.y;
            }
            int rA = row_base + mt * 16 + g;
            int rB = rA + 8;
            if (rA < M) {
                float2 o = make_float2(acc[mt][nt][0] + bx, acc[mt][nt][1] + by);
                *reinterpret_cast<float2*>(dstb + (size_t)rA * HID + col) = o;
            }
            if (rB < M) {
                float2 o = make_float2(acc[mt][nt][2] + bx, acc[mt][nt][3] + by);
                *reinterpret_cast<float2*>(dstb + (size_t)rB * HID + col) = o;
            }
        }
    }
}

// ---------------- edge scatter (R4 win, unchanged) ----------------
__global__ void edge_kernel(const int* __restrict__ src,
                            const int* __restrict__ dst,
                            int E, int N) {
    int warp = (blockIdx.x * blockDim.x + threadIdx.x) >> 5;
    int lane = threadIdx.x & 31;
    int base = warp * EPW;
    if (base >= E) return;

    int s[EPW], d[EPW];
    if (base + EPW <= E) {
        int4 sv = *reinterpret_cast<const int4*>(src + base);
        int4 dv = *reinterpret_cast<const int4*>(dst + base);
        s[0] = sv.x; s[1] = sv.y; s[2] = sv.z; s[3] = sv.w;
        d[0] = dv.x; d[1] = dv.y; d[2] = dv.z; d[3] = dv.w;
    } else {
#pragma unroll
        for (int e = 0; e < EPW; e++) {
            int i = base + e;
            s[e] = (i < E) ? src[i] : 0;
            d[e] = (i < E) ? dst[i] : -1;
        }
    }

    float4 v[EPW];
#pragma unroll
    for (int e = 0; e < EPW; e++) {
        int ss = ((unsigned)s[e] < (unsigned)N) ? s[e] : 0;
        v[e] = *reinterpret_cast<const float4*>(g_msg + (size_t)ss * HID + lane * 4);
    }

#pragma unroll
    for (int e = 0; e < EPW; e++) {
        if ((unsigned)d[e] >= (unsigned)N || (unsigned)s[e] >= (unsigned)N) continue;
        float* p = g_sums + (size_t)d[e] * HID + lane * 4;
        asm volatile("red.global.add.v4.f32 [%0], {%1,%2,%3,%4};"
                     :: "l"(p), "f"(v[e].x), "f"(v[e].y), "f"(v[e].z), "f"(v[e].w)
                     : "memory");
    }

    if (lane < EPW) {
        int dd = d[lane];
        if ((unsigned)dd < (unsigned)N && base + lane < E) {
            asm volatile("red.global.add.f32 [%0], %1;"
                         :: "l"(g_deg + dd), "f"(1.0f) : "memory");
        }
    }
}

// ---------------- finalize ----------------
__global__ void finalize_kernel(float* __restrict__ out, int n) {
    int i = blockIdx.x * blockDim.x + threadIdx.x;
    long long total4 = (long long)n * (HID / 4);
    if (i >= total4) return;
    int node = i >> 5;
    float dg  = g_deg[node];
    float inv = 1.0f / fmaxf(dg, 1.0f);
    float4 s  = reinterpret_cast<const float4*>(g_sums)[i];
    float4 sp = reinterpret_cast<const float4*>(g_self)[i];
    float4 o;
    o.x = fmaxf(fmaf(s.x, inv, sp.x), 0.f);
    o.y = fmaxf(fmaf(s.y, inv, sp.y), 0.f);
    o.z = fmaxf(fmaf(s.z, inv, sp.z), 0.f);
    o.w = fmaxf(fmaf(s.w, inv, sp.w), 0.f);
    reinterpret_cast<float4*>(out)[i] = o;
}

// ---------------- launch ----------------
extern "C" void kernel_launch(void* const* d_in, const int* in_sizes, int n_in,
                              void* d_out, int out_size) {
    const float* h   = (const float*)d_in[0];
    const int*   src = (const int*)d_in[1];
    const int*   dst = (const int*)d_in[2];
    const float* We  = (const float*)d_in[3];
    const float* Ws  = (const float*)d_in[4];
    const float* b   = (const float*)d_in[5];
    float* out = (float*)d_out;

    const int N = in_sizes[0] / HID;   // 50000
    const int E = in_sizes[1];         // 800000

    zero_kernel<<<1184, 256>>>(N);
    prep_B<<<16, 256>>>(We, Ws);

    dim3 ggrid((N + 127) / 128, 2);
    gemm_mma<<<ggrid, 256>>>(h, b, N);

    int warps_needed  = (E + EPW - 1) / EPW;
    int blocks_needed = (warps_needed + 7) / 8;
    edge_kernel<<<blocks_needed, 256>>>(src, dst, E, N);

    finalize_kernel<<<((N * (HID / 4)) + 255) / 256, 256>>>(out, N);
}